// round 16
// baseline (speedup 1.0000x reference)
#include <cuda_runtime.h>

#define BB 4
#define LQ 512
#define LK 512
#define HH 256

#define CTX_ELEMS (BB*LQ*HH)
#define LOG2E2 2.885390081777927f   // 2*log2(e)

typedef unsigned long long ull;

static __device__ __align__(16) ull g_qd[BB*LQ*HH];  // Eq duplicated {v,v}, [b][q][h]
static __device__ float g_kT[BB*HH*LK];              // Ek transposed [b][h][k]
static __device__ float g_s [BB*LQ*LK];              // raw scores; ref = C - 2s
static __device__ float g_part[2*CTX_ELEMS];         // context split-K partials

__device__ __forceinline__ float ex2a(float x) {
    float e; asm("ex2.approx.ftz.f32 %0, %1;" : "=f"(e) : "f"(x)); return e;
}
__device__ __forceinline__ float rcpa(float x) {
    float r; asm("rcp.approx.ftz.f32 %0, %1;" : "=f"(r) : "f"(x)); return r;
}
__device__ __forceinline__ ull pk(float x, float y) {
    ull r; asm("mov.b64 %0, {%1, %2};" : "=l"(r) : "f"(x), "f"(y)); return r;
}
__device__ __forceinline__ void upk(ull v, float& x, float& y) {
    asm("mov.b64 {%0, %1}, %2;" : "=f"(x), "=f"(y) : "l"(v));
}
__device__ __forceinline__ ull fma2(ull a, ull b, ull c) {
    ull d; asm("fma.rn.f32x2 %0, %1, %2, %3;" : "=l"(d) : "l"(a), "l"(b), "l"(c)); return d;
}
__device__ __forceinline__ ull mul2(ull a, ull b) {
    ull d; asm("mul.rn.f32x2 %0, %1, %2;" : "=l"(d) : "l"(a), "l"(b)); return d;
}
__device__ __forceinline__ ull add2(ull a, ull b) {
    ull d; asm("add.rn.f32x2 %0, %1, %2;" : "=l"(d) : "l"(a), "l"(b)); return d;
}
__device__ __forceinline__ ull lds2(const float* p) {
    return *(const ull*)p;
}

// ---------------------------------------------------------------------------
// K1: projections + exp epilogue. Double-buffered smem + register prefetch,
// packed f32x2 inner loop.
// z=0: g_qd[b][q][h] = {e,e}, e = exp(2*(q@WqT+bq))   (pre-duplicated!)
// z=1: g_kT[b][h][k] transposed via smem -> coalesced stores.
// ---------------------------------------------------------------------------
__global__ __launch_bounds__(256) void proj_kernel(
    const float* __restrict__ query, const float* __restrict__ values,
    const float* __restrict__ Wq, const float* __restrict__ bq,
    const float* __restrict__ Wk, const float* __restrict__ bk)
{
    const float* in   = blockIdx.z ? values : query;
    const float* W    = blockIdx.z ? Wk : Wq;
    const float* bias = blockIdx.z ? bk : bq;

    __shared__ float As[2][32][68];
    __shared__ float Bs[2][32][68];

    int tid = threadIdx.x;
    int tx = tid & 15, ty = tid >> 4;
    int m0 = blockIdx.x * 64, n0 = blockIdx.y * 64;

    int row0 = tid >> 3,         c40 = tid & 7;
    int row1 = (tid + 256) >> 3, c41 = (tid + 256) & 7;

    float4 ra0, ra1, rb0, rb1;
    ra0 = *(const float4*)&in[(size_t)(m0 + row0) * HH + c40 * 4];
    rb0 = *(const float4*)&W [(size_t)(n0 + row0) * HH + c40 * 4];
    ra1 = *(const float4*)&in[(size_t)(m0 + row1) * HH + c41 * 4];
    rb1 = *(const float4*)&W [(size_t)(n0 + row1) * HH + c41 * 4];

    As[0][c40*4+0][row0] = ra0.x; As[0][c40*4+1][row0] = ra0.y;
    As[0][c40*4+2][row0] = ra0.z; As[0][c40*4+3][row0] = ra0.w;
    Bs[0][c40*4+0][row0] = rb0.x; Bs[0][c40*4+1][row0] = rb0.y;
    Bs[0][c40*4+2][row0] = rb0.z; Bs[0][c40*4+3][row0] = rb0.w;
    As[0][c41*4+0][row1] = ra1.x; As[0][c41*4+1][row1] = ra1.y;
    As[0][c41*4+2][row1] = ra1.z; As[0][c41*4+3][row1] = ra1.w;
    Bs[0][c41*4+0][row1] = rb1.x; Bs[0][c41*4+1][row1] = rb1.y;
    Bs[0][c41*4+2][row1] = rb1.z; Bs[0][c41*4+3][row1] = rb1.w;
    __syncthreads();

    ull acc2[4][2] = {};
    int buf = 0;

    #pragma unroll 1
    for (int it = 0; it < HH / 32; it++) {
        int k1 = (it + 1) * 32;
        bool more = (it + 1 < HH / 32);
        if (more) {
            ra0 = *(const float4*)&in[(size_t)(m0 + row0) * HH + k1 + c40 * 4];
            rb0 = *(const float4*)&W [(size_t)(n0 + row0) * HH + k1 + c40 * 4];
            ra1 = *(const float4*)&in[(size_t)(m0 + row1) * HH + k1 + c41 * 4];
            rb1 = *(const float4*)&W [(size_t)(n0 + row1) * HH + k1 + c41 * 4];
        }
        #pragma unroll 8
        for (int kk = 0; kk < 32; kk++) {
            float4 a = *(const float4*)&As[buf][kk][ty * 4];
            ulonglong2 b = *(const ulonglong2*)&Bs[buf][kk][tx * 4];
            ull a0 = pk(a.x, a.x), a1 = pk(a.y, a.y);
            ull a2 = pk(a.z, a.z), a3 = pk(a.w, a.w);
            acc2[0][0] = fma2(a0, b.x, acc2[0][0]);
            acc2[0][1] = fma2(a0, b.y, acc2[0][1]);
            acc2[1][0] = fma2(a1, b.x, acc2[1][0]);
            acc2[1][1] = fma2(a1, b.y, acc2[1][1]);
            acc2[2][0] = fma2(a2, b.x, acc2[2][0]);
            acc2[2][1] = fma2(a2, b.y, acc2[2][1]);
            acc2[3][0] = fma2(a3, b.x, acc2[3][0]);
            acc2[3][1] = fma2(a3, b.y, acc2[3][1]);
        }
        if (more) {
            int nb = buf ^ 1;
            As[nb][c40*4+0][row0] = ra0.x; As[nb][c40*4+1][row0] = ra0.y;
            As[nb][c40*4+2][row0] = ra0.z; As[nb][c40*4+3][row0] = ra0.w;
            Bs[nb][c40*4+0][row0] = rb0.x; Bs[nb][c40*4+1][row0] = rb0.y;
            Bs[nb][c40*4+2][row0] = rb0.z; Bs[nb][c40*4+3][row0] = rb0.w;
            As[nb][c41*4+0][row1] = ra1.x; As[nb][c41*4+1][row1] = ra1.y;
            As[nb][c41*4+2][row1] = ra1.z; As[nb][c41*4+3][row1] = ra1.w;
            Bs[nb][c41*4+0][row1] = rb1.x; Bs[nb][c41*4+1][row1] = rb1.y;
            Bs[nb][c41*4+2][row1] = rb1.z; Bs[nb][c41*4+3][row1] = rb1.w;
        }
        __syncthreads();
        buf ^= 1;
    }

    float acc[4][4];
    #pragma unroll
    for (int i = 0; i < 4; i++) {
        upk(acc2[i][0], acc[i][0], acc[i][1]);
        upk(acc2[i][1], acc[i][2], acc[i][3]);
    }

    if (blockIdx.z == 0) {
        #pragma unroll
        for (int i = 0; i < 4; i++)
            #pragma unroll
            for (int j = 0; j < 4; j++) {
                int m = m0 + ty * 4 + i;
                int n = n0 + tx * 4 + j;
                float e = ex2a((acc[i][j] + bias[n]) * LOG2E2);
                g_qd[(size_t)m * HH + n] = pk(e, e);
            }
    } else {
        // transpose through smem (reuse As: 2*32*68 = 4352 floats = 64*68)
        float (*T)[68] = (float (*)[68])As;
        #pragma unroll
        for (int i = 0; i < 4; i++)
            #pragma unroll
            for (int j = 0; j < 4; j++) {
                int n = n0 + tx * 4 + j;
                T[tx * 4 + j][ty * 4 + i] = ex2a((acc[i][j] + bias[n]) * LOG2E2);
            }
        __syncthreads();
        int b_    = m0 / LK;
        int mbase = m0 % LK;
        int hl = tid >> 2;
        int kc = tid & 3;
        float* dst = &g_kT[((size_t)(b_ * HH) + n0 + hl) * LK + mbase + kc * 16];
        #pragma unroll
        for (int ii = 0; ii < 4; ii++)
            *(float4*)&dst[ii * 4] = *(const float4*)&T[hl][kc * 16 + ii * 4];
    }
}

// ---------------------------------------------------------------------------
// K2: scores — R14 best config (64q x 64k, single wave, pair-rcp packed),
// with eqp loaded PRE-DUPLICATED from g_qd via ulonglong2 (LDG.128 straight
// into register pairs — removes 128 pk-MOVs per thread vs R14).
// ---------------------------------------------------------------------------
__global__ __launch_bounds__(256) void score_kernel(const float* __restrict__ We)
{
    __shared__ float eks[256][32];   // 32 KB, swizzled

    int b  = blockIdx.z;
    int q0 = blockIdx.x * 64;
    int k0 = blockIdx.y * 64;
    int tid  = threadIdx.x;
    int lane = tid & 31;
    int hc   = lane & 15;
    int qh   = lane >> 4;
    int w    = tid >> 5;

    int s_kp = tid & 15;
    int s_hh = tid >> 4;

    const ull ONE2 = pk(1.0f, 1.0f);

    ull wep[16];
    {
        const float4* wp = (const float4*)(We + hc * 16);
        float4 w0 = wp[0], w1 = wp[1], w2 = wp[2], w3 = wp[3];
        wep[0]=pk(w0.x,w0.x); wep[1]=pk(w0.y,w0.y); wep[2]=pk(w0.z,w0.z); wep[3]=pk(w0.w,w0.w);
        wep[4]=pk(w1.x,w1.x); wep[5]=pk(w1.y,w1.y); wep[6]=pk(w1.z,w1.z); wep[7]=pk(w1.w,w1.w);
        wep[8]=pk(w2.x,w2.x); wep[9]=pk(w2.y,w2.y); wep[10]=pk(w2.z,w2.z); wep[11]=pk(w2.w,w2.w);
        wep[12]=pk(w3.x,w3.x); wep[13]=pk(w3.y,w3.y); wep[14]=pk(w3.z,w3.z); wep[15]=pk(w3.w,w3.w);
    }

    #pragma unroll 1
    for (int st = 0; st < 2; st++) {
        int kb = k0 + st * 32;
        __syncthreads();
        #pragma unroll
        for (int i = 0; i < 16; i++) {
            int h = s_hh + 16 * i;
            ull v = *(const ull*)(g_kT + ((size_t)(b * HH + h)) * LK + kb + 2 * s_kp);
            *(ull*)&eks[h][(s_kp ^ i) * 2] = v;
        }
        __syncthreads();

        #pragma unroll 1
        for (int qp = 0; qp < 4; qp++) {
            int q = q0 + qp * 16 + w * 2 + qh;
            // pre-duplicated Eq: straight LDG.128 into register pairs, no MOVs
            ull eqp[16];
            {
                const ulonglong2* ep =
                    (const ulonglong2*)(g_qd + ((size_t)(b * LQ) + q) * HH + hc * 16);
                #pragma unroll
                for (int i = 0; i < 8; i++) {
                    ulonglong2 v = ep[i];
                    eqp[2*i]   = v.x;
                    eqp[2*i+1] = v.y;
                }
            }
            float* srow = g_s + ((size_t)(b * LQ) + q) * LK + kb;

            #pragma unroll 4
            for (int t = 0; t < 16; t++) {
                int pc = (t ^ hc) * 2;
                ull accE = 0ull, accO = 0ull;
                #pragma unroll
                for (int jq = 0; jq < 4; jq++) {
                    const float* rb = &eks[16 * hc + 4 * jq][pc];
                    ull e0 = lds2(rb);
                    ull e1 = lds2(rb + 32);
                    ull e2 = lds2(rb + 64);
                    ull e3 = lds2(rb + 96);
                    ull t0 = fma2(e0, eqp[4*jq+0], ONE2);
                    ull t1 = fma2(e1, eqp[4*jq+1], ONE2);
                    ull t2 = fma2(e2, eqp[4*jq+2], ONE2);
                    ull t3 = fma2(e3, eqp[4*jq+3], ONE2);
                    // pair 01
                    ull d01 = mul2(t0, t1);
                    ull n01 = fma2(wep[4*jq+0], t1, mul2(wep[4*jq+1], t0));
                    float a01, b01; upk(d01, a01, b01);
                    ull r01 = pk(rcpa(a01), rcpa(b01));
                    accE = fma2(n01, r01, accE);
                    // pair 23
                    ull d23 = mul2(t2, t3);
                    ull n23 = fma2(wep[4*jq+2], t3, mul2(wep[4*jq+3], t2));
                    float a23, b23; upk(d23, a23, b23);
                    ull r23 = pk(rcpa(a23), rcpa(b23));
                    accO = fma2(n23, r23, accO);
                }
                ull accT = add2(accE, accO);
                float a0, a1; upk(accT, a0, a1);
                a0 += __shfl_xor_sync(0xffffffffu, a0, 1);
                a1 += __shfl_xor_sync(0xffffffffu, a1, 1);
                a0 += __shfl_xor_sync(0xffffffffu, a0, 2);
                a1 += __shfl_xor_sync(0xffffffffu, a1, 2);
                a0 += __shfl_xor_sync(0xffffffffu, a0, 4);
                a1 += __shfl_xor_sync(0xffffffffu, a1, 4);
                a0 += __shfl_xor_sync(0xffffffffu, a0, 8);
                a1 += __shfl_xor_sync(0xffffffffu, a1, 8);
                if (hc == 0)
                    *(float2*)&srow[2 * t] = make_float2(a0, a1);
            }
        }
    }
}

// ---------------------------------------------------------------------------
// K2b: softmax over k of score = -2*s. Warp per row.
// ---------------------------------------------------------------------------
__global__ __launch_bounds__(256) void softmax_kernel(float* __restrict__ attn)
{
    int row  = blockIdx.x * 8 + (threadIdx.x >> 5);
    int lane = threadIdx.x & 31;
    const float* s = g_s + (size_t)row * LK;

    float vals[16];
    float m = -1e30f;
    #pragma unroll
    for (int i = 0; i < 16; i++) {
        vals[i] = -2.0f * s[lane + 32 * i];
        m = fmaxf(m, vals[i]);
    }
    #pragma unroll
    for (int o = 16; o; o >>= 1) m = fmaxf(m, __shfl_xor_sync(0xffffffffu, m, o));
    float sum = 0.0f;
    #pragma unroll
    for (int i = 0; i < 16; i++) {
        vals[i] = ex2a((vals[i] - m) * 1.4426950408889634f);
        sum += vals[i];
    }
    #pragma unroll
    for (int o = 16; o; o >>= 1) sum += __shfl_xor_sync(0xffffffffu, sum, o);
    float inv = 1.0f / sum;

    float* arow = attn + (size_t)row * LK;
    #pragma unroll
    for (int i = 0; i < 16; i++)
        arow[lane + 32 * i] = vals[i] * inv;
}

// ---------------------------------------------------------------------------
// K3: context partials = attn @ values, split-K2, packed f32x2 inner
// (R8/R14 config — best measured).
// ---------------------------------------------------------------------------
__global__ __launch_bounds__(256) void context_kernel(
    const float* __restrict__ values, const float* __restrict__ attn)
{
    __shared__ float As[2][32][68];
    __shared__ float Vs[2][32][68];

    int tid = threadIdx.x;
    int b  = blockIdx.z >> 1;
    int ks = blockIdx.z & 1;
    int q0 = blockIdx.x * 64;
    int n0 = blockIdx.y * 64;
    int tx = tid & 15, ty = tid >> 4;
    int kbase = ks * (LK / 2);

    const float* Abase = attn + (size_t)b * LQ * LK + kbase;
    const float* Vbase = values + (size_t)(b * LK + kbase) * HH;

    int arow0 = tid >> 3,         ac40 = tid & 7;
    int arow1 = (tid + 256) >> 3, ac41 = (tid + 256) & 7;
    int vk0 = tid >> 4,           vc40 = tid & 15;
    int vk1 = (tid + 256) >> 4,   vc41 = (tid + 256) & 15;

    float4 ra0, ra1, rv0, rv1;
    ra0 = *(const float4*)&Abase[(size_t)(q0 + arow0) * LK + ac40 * 4];
    ra1 = *(const float4*)&Abase[(size_t)(q0 + arow1) * LK + ac41 * 4];
    rv0 = *(const float4*)&Vbase[(size_t)vk0 * HH + n0 + vc40 * 4];
    rv1 = *(const float4*)&Vbase[(size_t)vk1 * HH + n0 + vc41 * 4];

    As[0][ac40*4+0][arow0] = ra0.x; As[0][ac40*4+1][arow0] = ra0.y;
    As[0][ac40*4+2][arow0] = ra0.z; As[0][ac40*4+3][arow0] = ra0.w;
    As[0][ac41*4+0][arow1] = ra1.x; As[0][ac41*4+1][arow1] = ra1.y;
    As[0][ac41*4+2][arow1] = ra1.z; As[0][ac41*4+3][arow1] = ra1.w;
    *(float4*)&Vs[0][vk0][vc40 * 4] = rv0;
    *(float4*)&Vs[0][vk1][vc41 * 4] = rv1;
    __syncthreads();

    ull acc2[4][2] = {};
    int buf = 0;

    #pragma unroll 1
    for (int it = 0; it < (LK / 2) / 32; it++) {
        int k1 = (it + 1) * 32;
        bool more = (it + 1 < (LK / 2) / 32);
        if (more) {
            ra0 = *(const float4*)&Abase[(size_t)(q0 + arow0) * LK + k1 + ac40 * 4];
            ra1 = *(const float4*)&Abase[(size_t)(q0 + arow1) * LK + k1 + ac41 * 4];
            rv0 = *(const float4*)&Vbase[(size_t)(k1 + vk0) * HH + n0 + vc40 * 4];
            rv1 = *(const float4*)&Vbase[(size_t)(k1 + vk1) * HH + n0 + vc41 * 4];
        }
        #pragma unroll 8
        for (int kk = 0; kk < 32; kk++) {
            float4 a = *(const float4*)&As[buf][kk][ty * 4];
            ulonglong2 v = *(const ulonglong2*)&Vs[buf][kk][tx * 4];
            ull a0 = pk(a.x, a.x), a1 = pk(a.y, a.y);
            ull a2 = pk(a.z, a.z), a3 = pk(a.w, a.w);
            acc2[0][0] = fma2(a0, v.x, acc2[0][0]);
            acc2[0][1] = fma2(a0, v.y, acc2[0][1]);
            acc2[1][0] = fma2(a1, v.x, acc2[1][0]);
            acc2[1][1] = fma2(a1, v.y, acc2[1][1]);
            acc2[2][0] = fma2(a2, v.x, acc2[2][0]);
            acc2[2][1] = fma2(a2, v.y, acc2[2][1]);
            acc2[3][0] = fma2(a3, v.x, acc2[3][0]);
            acc2[3][1] = fma2(a3, v.y, acc2[3][1]);
        }
        if (more) {
            int nb = buf ^ 1;
            As[nb][ac40*4+0][arow0] = ra0.x; As[nb][ac40*4+1][arow0] = ra0.y;
            As[nb][ac40*4+2][arow0] = ra0.z; As[nb][ac40*4+3][arow0] = ra0.w;
            As[nb][ac41*4+0][arow1] = ra1.x; As[nb][ac41*4+1][arow1] = ra1.y;
            As[nb][ac41*4+2][arow1] = ra1.z; As[nb][ac41*4+3][arow1] = ra1.w;
            *(float4*)&Vs[nb][vk0][vc40 * 4] = rv0;
            *(float4*)&Vs[nb][vk1][vc41 * 4] = rv1;
        }
        __syncthreads();
        buf ^= 1;
    }

    float* part = g_part + (size_t)ks * CTX_ELEMS;
    #pragma unroll
    for (int i = 0; i < 4; i++) {
        float4 r;
        upk(acc2[i][0], r.x, r.y);
        upk(acc2[i][1], r.z, r.w);
        *(float4*)&part[(size_t)(b * LQ + q0 + ty * 4 + i) * HH + n0 + tx * 4] = r;
    }
}

// K3b: ctx = part0 + part1
__global__ __launch_bounds__(256) void combine_kernel(float* __restrict__ ctx)
{
    int i = (blockIdx.x * 256 + threadIdx.x) * 4;
    float4 a = *(const float4*)&g_part[i];
    float4 b = *(const float4*)&g_part[CTX_ELEMS + i];
    *(float4*)&ctx[i] = make_float4(a.x + b.x, a.y + b.y, a.z + b.z, a.w + b.w);
}

// ---------------------------------------------------------------------------
// Launch: proj(+exp, Eq duplicated, K transposed) -> scores -> softmax ->
// context -> combine. Output: [context (B*LQ*H) | attention (B*LQ*LK)].
// be unused (softmax-invariant).
// ---------------------------------------------------------------------------
extern "C" void kernel_launch(void* const* d_in, const int* in_sizes, int n_in,
                              void* d_out, int out_size)
{
    const float* query  = (const float*)d_in[0];
    const float* values = (const float*)d_in[1];
    const float* Wq     = (const float*)d_in[2];
    const float* bq     = (const float*)d_in[3];
    const float* Wk     = (const float*)d_in[4];
    const float* bk     = (const float*)d_in[5];
    const float* We     = (const float*)d_in[6];
    // d_in[7] = be, softmax-invariant

    float* out  = (float*)d_out;
    float* ctx  = out;
    float* attn = out + CTX_ELEMS;

    proj_kernel<<<dim3(32, 4, 2), 256>>>(query, values, Wq, bq, Wk, bk);
    score_kernel<<<dim3(LQ / 64, LK / 64, BB), 256>>>(We);
    softmax_kernel<<<dim3(BB * LQ / 8), 256>>>(attn);
    context_kernel<<<dim3(8, 4, BB * 2), 256>>>(values, attn);
    combine_kernel<<<dim3(CTX_ELEMS / 1024), 256>>>(ctx);
}

// round 17
// speedup vs baseline: 1.1346x; 1.1346x over previous
#include <cuda_runtime.h>

#define BB 4
#define LQ 512
#define LK 512
#define HH 256

#define CTX_ELEMS (BB*LQ*HH)
#define LOG2E2 2.885390081777927f   // 2*log2(e)

static __device__ float g_q [BB*LQ*HH];     // Eq = exp(2*q_proj), [b][q][h]
static __device__ float g_kT[BB*HH*LK];     // Ek = exp(2*k_proj), TRANSPOSED [b][h][k]
static __device__ float g_s [BB*LQ*LK];     // raw scores; ref score = C - 2s (consts drop)
static __device__ float g_part[2*CTX_ELEMS];// context split-K partials

typedef unsigned long long ull;

__device__ __forceinline__ float ex2a(float x) {
    float e; asm("ex2.approx.ftz.f32 %0, %1;" : "=f"(e) : "f"(x)); return e;
}
__device__ __forceinline__ float rcpa(float x) {
    float r; asm("rcp.approx.ftz.f32 %0, %1;" : "=f"(r) : "f"(x)); return r;
}
__device__ __forceinline__ ull pk(float x, float y) {
    ull r; asm("mov.b64 %0, {%1, %2};" : "=l"(r) : "f"(x), "f"(y)); return r;
}
__device__ __forceinline__ void upk(ull v, float& x, float& y) {
    asm("mov.b64 {%0, %1}, %2;" : "=f"(x), "=f"(y) : "l"(v));
}
__device__ __forceinline__ ull fma2(ull a, ull b, ull c) {
    ull d; asm("fma.rn.f32x2 %0, %1, %2, %3;" : "=l"(d) : "l"(a), "l"(b), "l"(c)); return d;
}
__device__ __forceinline__ ull mul2(ull a, ull b) {
    ull d; asm("mul.rn.f32x2 %0, %1, %2;" : "=l"(d) : "l"(a), "l"(b)); return d;
}
__device__ __forceinline__ ull add2(ull a, ull b) {
    ull d; asm("add.rn.f32x2 %0, %1, %2;" : "=l"(d) : "l"(a), "l"(b)); return d;
}
__device__ __forceinline__ ull lds2(const float* p) {
    return *(const ull*)p;
}

// ---------------------------------------------------------------------------
// K1: projections + exp epilogue. Double-buffered smem + register prefetch,
// packed f32x2 inner loop.
// z=0: g_q[b][q][h] = exp(2*(q@WqT+bq))
// z=1: g_kT[b][h][k] transposed, via smem transpose -> coalesced stores.
// ---------------------------------------------------------------------------
__global__ __launch_bounds__(256) void proj_kernel(
    const float* __restrict__ query, const float* __restrict__ values,
    const float* __restrict__ Wq, const float* __restrict__ bq,
    const float* __restrict__ Wk, const float* __restrict__ bk)
{
    const float* in   = blockIdx.z ? values : query;
    const float* W    = blockIdx.z ? Wk : Wq;
    const float* bias = blockIdx.z ? bk : bq;

    __shared__ float As[2][32][68];
    __shared__ float Bs[2][32][68];

    int tid = threadIdx.x;
    int tx = tid & 15, ty = tid >> 4;
    int m0 = blockIdx.x * 64, n0 = blockIdx.y * 64;

    int row0 = tid >> 3,         c40 = tid & 7;
    int row1 = (tid + 256) >> 3, c41 = (tid + 256) & 7;

    float4 ra0, ra1, rb0, rb1;
    ra0 = *(const float4*)&in[(size_t)(m0 + row0) * HH + c40 * 4];
    rb0 = *(const float4*)&W [(size_t)(n0 + row0) * HH + c40 * 4];
    ra1 = *(const float4*)&in[(size_t)(m0 + row1) * HH + c41 * 4];
    rb1 = *(const float4*)&W [(size_t)(n0 + row1) * HH + c41 * 4];

    As[0][c40*4+0][row0] = ra0.x; As[0][c40*4+1][row0] = ra0.y;
    As[0][c40*4+2][row0] = ra0.z; As[0][c40*4+3][row0] = ra0.w;
    Bs[0][c40*4+0][row0] = rb0.x; Bs[0][c40*4+1][row0] = rb0.y;
    Bs[0][c40*4+2][row0] = rb0.z; Bs[0][c40*4+3][row0] = rb0.w;
    As[0][c41*4+0][row1] = ra1.x; As[0][c41*4+1][row1] = ra1.y;
    As[0][c41*4+2][row1] = ra1.z; As[0][c41*4+3][row1] = ra1.w;
    Bs[0][c41*4+0][row1] = rb1.x; Bs[0][c41*4+1][row1] = rb1.y;
    Bs[0][c41*4+2][row1] = rb1.z; Bs[0][c41*4+3][row1] = rb1.w;
    __syncthreads();

    ull acc2[4][2] = {};
    int buf = 0;

    #pragma unroll 1
    for (int it = 0; it < HH / 32; it++) {
        int k1 = (it + 1) * 32;
        bool more = (it + 1 < HH / 32);
        if (more) {
            ra0 = *(const float4*)&in[(size_t)(m0 + row0) * HH + k1 + c40 * 4];
            rb0 = *(const float4*)&W [(size_t)(n0 + row0) * HH + k1 + c40 * 4];
            ra1 = *(const float4*)&in[(size_t)(m0 + row1) * HH + k1 + c41 * 4];
            rb1 = *(const float4*)&W [(size_t)(n0 + row1) * HH + k1 + c41 * 4];
        }
        #pragma unroll 8
        for (int kk = 0; kk < 32; kk++) {
            float4 a = *(const float4*)&As[buf][kk][ty * 4];
            ulonglong2 b = *(const ulonglong2*)&Bs[buf][kk][tx * 4];
            ull a0 = pk(a.x, a.x), a1 = pk(a.y, a.y);
            ull a2 = pk(a.z, a.z), a3 = pk(a.w, a.w);
            acc2[0][0] = fma2(a0, b.x, acc2[0][0]);
            acc2[0][1] = fma2(a0, b.y, acc2[0][1]);
            acc2[1][0] = fma2(a1, b.x, acc2[1][0]);
            acc2[1][1] = fma2(a1, b.y, acc2[1][1]);
            acc2[2][0] = fma2(a2, b.x, acc2[2][0]);
            acc2[2][1] = fma2(a2, b.y, acc2[2][1]);
            acc2[3][0] = fma2(a3, b.x, acc2[3][0]);
            acc2[3][1] = fma2(a3, b.y, acc2[3][1]);
        }
        if (more) {
            int nb = buf ^ 1;
            As[nb][c40*4+0][row0] = ra0.x; As[nb][c40*4+1][row0] = ra0.y;
            As[nb][c40*4+2][row0] = ra0.z; As[nb][c40*4+3][row0] = ra0.w;
            Bs[nb][c40*4+0][row0] = rb0.x; Bs[nb][c40*4+1][row0] = rb0.y;
            Bs[nb][c40*4+2][row0] = rb0.z; Bs[nb][c40*4+3][row0] = rb0.w;
            As[nb][c41*4+0][row1] = ra1.x; As[nb][c41*4+1][row1] = ra1.y;
            As[nb][c41*4+2][row1] = ra1.z; As[nb][c41*4+3][row1] = ra1.w;
            Bs[nb][c41*4+0][row1] = rb1.x; Bs[nb][c41*4+1][row1] = rb1.y;
            Bs[nb][c41*4+2][row1] = rb1.z; Bs[nb][c41*4+3][row1] = rb1.w;
        }
        __syncthreads();
        buf ^= 1;
    }

    float acc[4][4];
    #pragma unroll
    for (int i = 0; i < 4; i++) {
        upk(acc2[i][0], acc[i][0], acc[i][1]);
        upk(acc2[i][1], acc[i][2], acc[i][3]);
    }

    if (blockIdx.z == 0) {
        #pragma unroll
        for (int i = 0; i < 4; i++)
            #pragma unroll
            for (int j = 0; j < 4; j++) {
                int m = m0 + ty * 4 + i;
                int n = n0 + tx * 4 + j;
                g_q[(size_t)m * HH + n] = ex2a((acc[i][j] + bias[n]) * LOG2E2);
            }
    } else {
        // transpose through smem (reuse As: 2*32*68 = 4352 floats = 64*68)
        float (*T)[68] = (float (*)[68])As;
        #pragma unroll
        for (int i = 0; i < 4; i++)
            #pragma unroll
            for (int j = 0; j < 4; j++) {
                int n = n0 + tx * 4 + j;
                T[tx * 4 + j][ty * 4 + i] = ex2a((acc[i][j] + bias[n]) * LOG2E2);
            }
        __syncthreads();
        int b_    = m0 / LK;
        int mbase = m0 % LK;
        int hl = tid >> 2;         // 0..63 (h within tile)
        int kc = tid & 3;          // 0..3  (16-float chunk of k)
        float* dst = &g_kT[((size_t)(b_ * HH) + n0 + hl) * LK + mbase + kc * 16];
        #pragma unroll
        for (int ii = 0; ii < 4; ii++)
            *(float4*)&dst[ii * 4] = *(const float4*)&T[hl][kc * 16 + ii * 4];
    }
}

// ---------------------------------------------------------------------------
// K2: scores — R14 best config (64q x 64k single wave, pair-rcp packed),
// with PACKED 64-bit shfl reduction: (a0,a1) reduced as one ull via add2
// (8 SHFL + 4 ADD2 vs 8 SHFL + 8 FADD; accE/accO merge folds in).
// ---------------------------------------------------------------------------
__global__ __launch_bounds__(256) void score_kernel(const float* __restrict__ We)
{
    __shared__ float eks[256][32];   // 32 KB, swizzled

    int b  = blockIdx.z;
    int q0 = blockIdx.x * 64;
    int k0 = blockIdx.y * 64;
    int tid  = threadIdx.x;
    int lane = tid & 31;
    int hc   = lane & 15;
    int qh   = lane >> 4;
    int w    = tid >> 5;

    int s_kp = tid & 15;     // staging: kpair
    int s_hh = tid >> 4;     // staging: h mod 16

    const ull ONE2 = pk(1.0f, 1.0f);

    ull wep[16];
    {
        const float4* wp = (const float4*)(We + hc * 16);
        float4 w0 = wp[0], w1 = wp[1], w2 = wp[2], w3 = wp[3];
        wep[0]=pk(w0.x,w0.x); wep[1]=pk(w0.y,w0.y); wep[2]=pk(w0.z,w0.z); wep[3]=pk(w0.w,w0.w);
        wep[4]=pk(w1.x,w1.x); wep[5]=pk(w1.y,w1.y); wep[6]=pk(w1.z,w1.z); wep[7]=pk(w1.w,w1.w);
        wep[8]=pk(w2.x,w2.x); wep[9]=pk(w2.y,w2.y); wep[10]=pk(w2.z,w2.z); wep[11]=pk(w2.w,w2.w);
        wep[12]=pk(w3.x,w3.x); wep[13]=pk(w3.y,w3.y); wep[14]=pk(w3.z,w3.z); wep[15]=pk(w3.w,w3.w);
    }

    #pragma unroll 1
    for (int st = 0; st < 2; st++) {
        int kb = k0 + st * 32;
        __syncthreads();
        #pragma unroll
        for (int i = 0; i < 16; i++) {
            int h = s_hh + 16 * i;
            ull v = *(const ull*)(g_kT + ((size_t)(b * HH + h)) * LK + kb + 2 * s_kp);
            *(ull*)&eks[h][(s_kp ^ i) * 2] = v;
        }
        __syncthreads();

        #pragma unroll 1
        for (int qp = 0; qp < 4; qp++) {
            int q = q0 + qp * 16 + w * 2 + qh;
            ull eqp[16];
            {
                const float4* ep = (const float4*)(g_q + ((size_t)(b * LQ) + q) * HH + hc * 16);
                float4 e0 = ep[0], e1 = ep[1], e2 = ep[2], e3 = ep[3];
                eqp[0]=pk(e0.x,e0.x); eqp[1]=pk(e0.y,e0.y); eqp[2]=pk(e0.z,e0.z); eqp[3]=pk(e0.w,e0.w);
                eqp[4]=pk(e1.x,e1.x); eqp[5]=pk(e1.y,e1.y); eqp[6]=pk(e1.z,e1.z); eqp[7]=pk(e1.w,e1.w);
                eqp[8]=pk(e2.x,e2.x); eqp[9]=pk(e2.y,e2.y); eqp[10]=pk(e2.z,e2.z); eqp[11]=pk(e2.w,e2.w);
                eqp[12]=pk(e3.x,e3.x); eqp[13]=pk(e3.y,e3.y); eqp[14]=pk(e3.z,e3.z); eqp[15]=pk(e3.w,e3.w);
            }
            float* srow = g_s + ((size_t)(b * LQ) + q) * LK + kb;

            #pragma unroll 4
            for (int t = 0; t < 16; t++) {
                int pc = (t ^ hc) * 2;
                ull accE = 0ull, accO = 0ull;
                #pragma unroll
                for (int jq = 0; jq < 4; jq++) {
                    const float* rb = &eks[16 * hc + 4 * jq][pc];
                    ull e0 = lds2(rb);
                    ull e1 = lds2(rb + 32);
                    ull e2 = lds2(rb + 64);
                    ull e3 = lds2(rb + 96);
                    ull t0 = fma2(e0, eqp[4*jq+0], ONE2);
                    ull t1 = fma2(e1, eqp[4*jq+1], ONE2);
                    ull t2 = fma2(e2, eqp[4*jq+2], ONE2);
                    ull t3 = fma2(e3, eqp[4*jq+3], ONE2);
                    // pair 01
                    ull d01 = mul2(t0, t1);
                    ull n01 = fma2(wep[4*jq+0], t1, mul2(wep[4*jq+1], t0));
                    float a01, b01; upk(d01, a01, b01);
                    ull r01 = pk(rcpa(a01), rcpa(b01));
                    accE = fma2(n01, r01, accE);
                    // pair 23
                    ull d23 = mul2(t2, t3);
                    ull n23 = fma2(wep[4*jq+2], t3, mul2(wep[4*jq+3], t2));
                    float a23, b23; upk(d23, a23, b23);
                    ull r23 = pk(rcpa(a23), rcpa(b23));
                    accO = fma2(n23, r23, accO);
                }
                // packed reduction over 16 hc lanes (ull shfl = 2x SHFL.b32,
                // add2 halves the FADD count)
                ull acc = add2(accE, accO);
                acc = add2(acc, __shfl_xor_sync(0xffffffffu, acc, 1));
                acc = add2(acc, __shfl_xor_sync(0xffffffffu, acc, 2));
                acc = add2(acc, __shfl_xor_sync(0xffffffffu, acc, 4));
                acc = add2(acc, __shfl_xor_sync(0xffffffffu, acc, 8));
                if (hc == 0) {
                    float a0, a1; upk(acc, a0, a1);
                    *(float2*)&srow[2 * t] = make_float2(a0, a1);
                }
            }
        }
    }
}

// ---------------------------------------------------------------------------
// K2b: softmax over k of score = -2*s. Warp per row. Constant-folded:
// p = (m - s) * 2*log2(e) per element (one FMA each), ex2.
// ---------------------------------------------------------------------------
__global__ __launch_bounds__(256) void softmax_kernel(float* __restrict__ attn)
{
    int row  = blockIdx.x * 8 + (threadIdx.x >> 5);
    int lane = threadIdx.x & 31;
    const float* s = g_s + (size_t)row * LK;

    float vals[16];
    float mn = 1e30f;                 // min of s == max of score (-2s)
    #pragma unroll
    for (int i = 0; i < 16; i++) {
        vals[i] = s[lane + 32 * i];
        mn = fminf(mn, vals[i]);
    }
    #pragma unroll
    for (int o = 16; o; o >>= 1) mn = fminf(mn, __shfl_xor_sync(0xffffffffu, mn, o));
    float sum = 0.0f;
    #pragma unroll
    for (int i = 0; i < 16; i++) {
        // score - max_score = -2*(s - mn); *log2e -> (mn - s)*LOG2E2
        vals[i] = ex2a((mn - vals[i]) * LOG2E2);
        sum += vals[i];
    }
    #pragma unroll
    for (int o = 16; o; o >>= 1) sum += __shfl_xor_sync(0xffffffffu, sum, o);
    float inv = 1.0f / sum;

    float* arow = attn + (size_t)row * LK;
    #pragma unroll
    for (int i = 0; i < 16; i++)
        arow[lane + 32 * i] = vals[i] * inv;
}

// ---------------------------------------------------------------------------
// K3: context partials = attn @ values, split-K2, packed f32x2 inner
// (R8/R14 config — best measured).
// ---------------------------------------------------------------------------
__global__ __launch_bounds__(256) void context_kernel(
    const float* __restrict__ values, const float* __restrict__ attn)
{
    __shared__ float As[2][32][68];
    __shared__ float Vs[2][32][68];

    int tid = threadIdx.x;
    int b  = blockIdx.z >> 1;
    int ks = blockIdx.z & 1;
    int q0 = blockIdx.x * 64;
    int n0 = blockIdx.y * 64;
    int tx = tid & 15, ty = tid >> 4;
    int kbase = ks * (LK / 2);

    const float* Abase = attn + (size_t)b * LQ * LK + kbase;
    const float* Vbase = values + (size_t)(b * LK + kbase) * HH;

    int arow0 = tid >> 3,         ac40 = tid & 7;
    int arow1 = (tid + 256) >> 3, ac41 = (tid + 256) & 7;
    int vk0 = tid >> 4,           vc40 = tid & 15;
    int vk1 = (tid + 256) >> 4,   vc41 = (tid + 256) & 15;

    float4 ra0, ra1, rv0, rv1;
    ra0 = *(const float4*)&Abase[(size_t)(q0 + arow0) * LK + ac40 * 4];
    ra1 = *(const float4*)&Abase[(size_t)(q0 + arow1) * LK + ac41 * 4];
    rv0 = *(const float4*)&Vbase[(size_t)vk0 * HH + n0 + vc40 * 4];
    rv1 = *(const float4*)&Vbase[(size_t)vk1 * HH + n0 + vc41 * 4];

    As[0][ac40*4+0][arow0] = ra0.x; As[0][ac40*4+1][arow0] = ra0.y;
    As[0][ac40*4+2][arow0] = ra0.z; As[0][ac40*4+3][arow0] = ra0.w;
    As[0][ac41*4+0][arow1] = ra1.x; As[0][ac41*4+1][arow1] = ra1.y;
    As[0][ac41*4+2][arow1] = ra1.z; As[0][ac41*4+3][arow1] = ra1.w;
    *(float4*)&Vs[0][vk0][vc40 * 4] = rv0;
    *(float4*)&Vs[0][vk1][vc41 * 4] = rv1;
    __syncthreads();

    ull acc2[4][2] = {};
    int buf = 0;

    #pragma unroll 1
    for (int it = 0; it < (LK / 2) / 32; it++) {
        int k1 = (it + 1) * 32;
        bool more = (it + 1 < (LK / 2) / 32);
        if (more) {
            ra0 = *(const float4*)&Abase[(size_t)(q0 + arow0) * LK + k1 + ac40 * 4];
            ra1 = *(const float4*)&Abase[(size_t)(q0 + arow1) * LK + k1 + ac41 * 4];
            rv0 = *(const float4*)&Vbase[(size_t)(k1 + vk0) * HH + n0 + vc40 * 4];
            rv1 = *(const float4*)&Vbase[(size_t)(k1 + vk1) * HH + n0 + vc41 * 4];
        }
        #pragma unroll 8
        for (int kk = 0; kk < 32; kk++) {
            float4 a = *(const float4*)&As[buf][kk][ty * 4];
            ulonglong2 v = *(const ulonglong2*)&Vs[buf][kk][tx * 4];
            ull a0 = pk(a.x, a.x), a1 = pk(a.y, a.y);
            ull a2 = pk(a.z, a.z), a3 = pk(a.w, a.w);
            acc2[0][0] = fma2(a0, v.x, acc2[0][0]);
            acc2[0][1] = fma2(a0, v.y, acc2[0][1]);
            acc2[1][0] = fma2(a1, v.x, acc2[1][0]);
            acc2[1][1] = fma2(a1, v.y, acc2[1][1]);
            acc2[2][0] = fma2(a2, v.x, acc2[2][0]);
            acc2[2][1] = fma2(a2, v.y, acc2[2][1]);
            acc2[3][0] = fma2(a3, v.x, acc2[3][0]);
            acc2[3][1] = fma2(a3, v.y, acc2[3][1]);
        }
        if (more) {
            int nb = buf ^ 1;
            As[nb][ac40*4+0][arow0] = ra0.x; As[nb][ac40*4+1][arow0] = ra0.y;
            As[nb][ac40*4+2][arow0] = ra0.z; As[nb][ac40*4+3][arow0] = ra0.w;
            As[nb][ac41*4+0][arow1] = ra1.x; As[nb][ac41*4+1][arow1] = ra1.y;
            As[nb][ac41*4+2][arow1] = ra1.z; As[nb][ac41*4+3][arow1] = ra1.w;
            *(float4*)&Vs[nb][vk0][vc40 * 4] = rv0;
            *(float4*)&Vs[nb][vk1][vc41 * 4] = rv1;
        }
        __syncthreads();
        buf ^= 1;
    }

    float* part = g_part + (size_t)ks * CTX_ELEMS;
    #pragma unroll
    for (int i = 0; i < 4; i++) {
        float4 r;
        upk(acc2[i][0], r.x, r.y);
        upk(acc2[i][1], r.z, r.w);
        *(float4*)&part[(size_t)(b * LQ + q0 + ty * 4 + i) * HH + n0 + tx * 4] = r;
    }
}

// K3b: ctx = part0 + part1
__global__ __launch_bounds__(256) void combine_kernel(float* __restrict__ ctx)
{
    int i = (blockIdx.x * 256 + threadIdx.x) * 4;
    float4 a = *(const float4*)&g_part[i];
    float4 b = *(const float4*)&g_part[CTX_ELEMS + i];
    *(float4*)&ctx[i] = make_float4(a.x + b.x, a.y + b.y, a.z + b.z, a.w + b.w);
}

// ---------------------------------------------------------------------------
// Launch: proj(+exp, K transposed) -> scores -> softmax -> context -> combine.
// Output layout: [context (B*LQ*H) | attention (B*LQ*LK)]. be unused.
// ---------------------------------------------------------------------------
extern "C" void kernel_launch(void* const* d_in, const int* in_sizes, int n_in,
                              void* d_out, int out_size)
{
    const float* query  = (const float*)d_in[0];
    const float* values = (const float*)d_in[1];
    const float* Wq     = (const float*)d_in[2];
    const float* bq     = (const float*)d_in[3];
    const float* Wk     = (const float*)d_in[4];
    const float* bk     = (const float*)d_in[5];
    const float* We     = (const float*)d_in[6];
    // d_in[7] = be, softmax-invariant

    float* out  = (float*)d_out;
    float* ctx  = out;
    float* attn = out + CTX_ELEMS;

    proj_kernel<<<dim3(32, 4, 2), 256>>>(query, values, Wq, bq, Wk, bk);
    score_kernel<<<dim3(LQ / 64, LK / 64, BB), 256>>>(We);
    softmax_kernel<<<dim3(BB * LQ / 8), 256>>>(attn);
    context_kernel<<<dim3(8, 4, BB * 2), 256>>>(values, attn);
    combine_kernel<<<dim3(CTX_ELEMS / 1024), 256>>>(ctx);
}